// round 4
// baseline (speedup 1.0000x reference)
#include <cuda_runtime.h>
#include <cuda_bf16.h>
#include <cstdint>
#include <cstddef>

#define BATCH 4
#define C_IN  124
#define CP    128
#define NPIX  4096
#define NIT   32

// ---------------- device scratch (zero-init; padding cols 124..127 stay 0) ----
__device__ __align__(128) __nv_bfloat16 g_hiT[BATCH * NPIX * CP];   // BfT [b][n][c] bf16
__device__ __align__(128) float         g_r2 [2][BATCH * NPIX];     // partial row norms

// ---------------- helpers ----------------
__device__ __forceinline__ uint32_t smem_u32(const void* p) {
    uint32_t a;
    asm("{ .reg .u64 t; cvta.to.shared.u64 t, %1; cvt.u32.u64 %0, t; }" : "=r"(a) : "l"(p));
    return a;
}
#define LDSM_X4(r, addr) \
    asm volatile("ldmatrix.sync.aligned.m8n8.x4.shared.b16 {%0,%1,%2,%3}, [%4];" \
        : "=r"((r)[0]), "=r"((r)[1]), "=r"((r)[2]), "=r"((r)[3]) : "r"(addr))
#define LDSM_X4_T(r, addr) \
    asm volatile("ldmatrix.sync.aligned.m8n8.x4.trans.shared.b16 {%0,%1,%2,%3}, [%4];" \
        : "=r"((r)[0]), "=r"((r)[1]), "=r"((r)[2]), "=r"((r)[3]) : "r"(addr))
#define MMA_16816(c, a, b0, b1) \
    asm volatile("mma.sync.aligned.m16n8k16.row.col.f32.bf16.bf16.f32 " \
        "{%0,%1,%2,%3}, {%4,%5,%6,%7}, {%8,%9}, {%0,%1,%2,%3};" \
        : "+f"((c)[0]), "+f"((c)[1]), "+f"((c)[2]), "+f"((c)[3]) \
        : "r"((a)[0]), "r"((a)[1]), "r"((a)[2]), "r"((a)[3]), "r"(b0), "r"(b1))

__device__ __forceinline__ uint32_t pack_bf16x2(float even, float odd) {
    uint32_t r;
    asm("cvt.rn.satfinite.bf16x2.f32 %0, %1, %2;" : "=r"(r) : "f"(odd), "f"(even));
    return r;  // low half = even
}
__device__ __forceinline__ float bf_lo(uint32_t u) { return __uint_as_float(u << 16); }
__device__ __forceinline__ float bf_hi(uint32_t u) { return __uint_as_float(u & 0xffff0000u); }

// Copy a [128 rows][128 bf16] row-major gmem tile (row stride 128 elems) into
// smem with 16B-chunk XOR swizzle: byte(row, ch) = row*256 + ((ch ^ (row&7))<<4)
__device__ __forceinline__ void load_tile(char* dst, const __nv_bfloat16* src,
                                          int tid, int nthreads) {
    for (int idx = tid; idx < 2048; idx += nthreads) {
        int row = idx >> 4;
        int ch  = idx & 15;
        uint4 v = *reinterpret_cast<const uint4*>(src + (size_t)row * CP + (ch << 3));
        *reinterpret_cast<uint4*>(dst + row * 256 + (((ch ^ (row & 7)) << 4))) = v;
    }
}

// ================= kernel 1: BfT = (Wb @ x)^T in bf16, + row norms =================
// grid 128 = b(4) x ntile(16) x co-half(2); block 256; thread = 1 pixel, 62 c-outs.
__global__ void __launch_bounds__(256, 1)
k1_project(const float* __restrict__ x, const float* __restrict__ Wb) {
    extern __shared__ float sm1[];
    float* xs = sm1;                  // [124][256]
    float* ws = sm1 + 124 * 256;      // [62][124]

    int blk  = blockIdx.x;
    int half = blk & 1;
    int nt   = (blk >> 1) & 15;
    int b    = blk >> 5;
    int n0   = nt * 256;
    int co0  = half * 62;
    int tid  = threadIdx.x;

    for (int idx = tid; idx < 124 * 256; idx += 256) {
        int ci = idx >> 8, j = idx & 255;
        xs[idx] = x[((size_t)b * C_IN + ci) * NPIX + n0 + j];
    }
    for (int idx = tid; idx < 62 * 124; idx += 256)
        ws[idx] = Wb[(size_t)(co0 + idx / 124) * C_IN + (idx % 124)];
    __syncthreads();

    float acc[62];
#pragma unroll
    for (int j = 0; j < 62; j++) acc[j] = 0.f;
    for (int ci = 0; ci < 124; ci++) {
        float xv = xs[ci * 256 + tid];
#pragma unroll
        for (int j = 0; j < 62; j++) acc[j] += ws[j * 124 + ci] * xv;
    }
    __syncthreads();  // xs region reusable

    __nv_bfloat16* shh = reinterpret_cast<__nv_bfloat16*>(sm1);  // [256][62]
    float r = 0.f;
#pragma unroll
    for (int j = 0; j < 62; j++) {
        shh[tid * 62 + j] = __float2bfloat16(acc[j]);
        r += acc[j] * acc[j];
    }
    g_r2[half][b * NPIX + n0 + tid] = r;
    __syncthreads();

    for (int idx = tid; idx < 256 * 62; idx += 256) {
        int p = idx / 62, jj = idx - p * 62;
        g_hiT[((size_t)b * NPIX + n0 + p) * CP + co0 + jj] = shh[idx];
    }
}

// ================= kernel 2: fused flash attention (mma.sync bf16) =================
// grid 128 = b(4) x m-tile(32); block 512 = 16 warps, 4x4 grid of 32x32 warp tiles.
#define SM_Q   0
#define SM_K   32768
#define SM_P   65536
#define SM_RS  98304          // float[4][128] per-ni rowsum partials
#define SM_RT  100352         // float[128] running row totals
#define SM_RR  100864         // float[128] row norms
#define SM2_TOTAL 101504

__global__ void __launch_bounds__(512, 1)
k2_attn(const float* __restrict__ x, const float* __restrict__ gamma,
        float* __restrict__ out) {
    extern __shared__ char sm[];
    uint32_t sb = smem_u32(sm);
    float* RS = reinterpret_cast<float*>(sm + SM_RS);
    float* RT = reinterpret_cast<float*>(sm + SM_RT);
    float* RR = reinterpret_cast<float*>(sm + SM_RR);

    int tid = threadIdx.x;
    int l   = tid & 31, wid = tid >> 5;
    int mi  = wid >> 2, ni = wid & 3;
    int b   = blockIdx.x >> 5;
    int m0  = (blockIdx.x & 31) * 128;

    const __nv_bfloat16* hiT = g_hiT + (size_t)b * NPIX * CP;

    if (tid < 128) {
        RT[tid] = 0.f;
        RR[tid] = g_r2[0][b * NPIX + m0 + tid] + g_r2[1][b * NPIX + m0 + tid];
    }
    load_tile(sm + SM_Q, hiT + (size_t)m0 * CP, tid, 512);
    float gammav = gamma[0];
    __syncthreads();

    // per-lane ldmatrix address components
    int rowA = l & 15, hA = l >> 4, swzA = rowA & 7;       // A-pattern (Q, P, V-trans)
    int rowB = (l & 7) + ((l >> 4) << 3);                  // B-pattern (K)
    int pB   = (l >> 3) & 1, swzB = rowB & 7;
    uint32_t qbase[2], pbase[2], kbase[2];
#pragma unroll
    for (int mt = 0; mt < 2; mt++) {
        int r = mi * 32 + mt * 16 + rowA;
        qbase[mt] = sb + SM_Q + r * 256;
        pbase[mt] = sb + SM_P + r * 256;
    }
#pragma unroll
    for (int ntp = 0; ntp < 2; ntp++)
        kbase[ntp] = sb + SM_K + (ni * 32 + ntp * 16 + rowB) * 256;
    uint32_t vrowbase = sb + SM_K + rowA * 256;
    int vchunk[2] = { ni * 4 + hA, ni * 4 + 2 + hA };

    float rr[2][2];
#pragma unroll
    for (int mt = 0; mt < 2; mt++) {
        rr[mt][0] = RR[mi * 32 + mt * 16 + (l >> 2)];
        rr[mt][1] = RR[mi * 32 + mt * 16 + (l >> 2) + 8];
    }

    float oacc[2][4][4];
#pragma unroll
    for (int a = 0; a < 2; a++)
#pragma unroll
        for (int c = 0; c < 4; c++)
#pragma unroll
            for (int d = 0; d < 4; d++) oacc[a][c][d] = 0.f;

    for (int it = 0; it < NIT; it++) {
        load_tile(sm + SM_K, hiT + (size_t)(it * 128) * CP, tid, 512);
        __syncthreads();

        // ---- QK^T : S[32m x 32n] per warp ----
        float sacc[2][4][4];
#pragma unroll
        for (int a = 0; a < 2; a++)
#pragma unroll
            for (int c = 0; c < 4; c++)
#pragma unroll
                for (int d = 0; d < 4; d++) sacc[a][c][d] = 0.f;
#pragma unroll
        for (int ks = 0; ks < 8; ks++) {
            uint32_t af[2][4], bf[2][4];
            int chA = 2 * ks + hA, chB = 2 * ks + pB;
#pragma unroll
            for (int mt = 0; mt < 2; mt++) LDSM_X4(af[mt], qbase[mt] + ((chA ^ swzA) << 4));
#pragma unroll
            for (int ntp = 0; ntp < 2; ntp++) LDSM_X4(bf[ntp], kbase[ntp] + ((chB ^ swzB) << 4));
#pragma unroll
            for (int mt = 0; mt < 2; mt++)
#pragma unroll
                for (int nt = 0; nt < 4; nt++)
                    MMA_16816(sacc[mt][nt], af[mt], bf[nt >> 1][(nt & 1) * 2], bf[nt >> 1][(nt & 1) * 2 + 1]);
        }

        // ---- softmax: p = bf16(exp(s - ||B_m||^2)); rowsum from ROUNDED p ----
        float part[2][2] = {{0.f, 0.f}, {0.f, 0.f}};
        uint32_t pk[2][4][2];
#pragma unroll
        for (int mt = 0; mt < 2; mt++)
#pragma unroll
            for (int nt = 0; nt < 4; nt++) {
                float e0 = __expf(sacc[mt][nt][0] - rr[mt][0]);
                float e1 = __expf(sacc[mt][nt][1] - rr[mt][0]);
                float e2 = __expf(sacc[mt][nt][2] - rr[mt][1]);
                float e3 = __expf(sacc[mt][nt][3] - rr[mt][1]);
                uint32_t u01 = pack_bf16x2(e0, e1);
                uint32_t u23 = pack_bf16x2(e2, e3);
                pk[mt][nt][0] = u01;
                pk[mt][nt][1] = u23;
                part[mt][0] += bf_lo(u01) + bf_hi(u01);
                part[mt][1] += bf_lo(u23) + bf_hi(u23);
            }
#pragma unroll
        for (int mt = 0; mt < 2; mt++)
#pragma unroll
            for (int h2 = 0; h2 < 2; h2++) {
                float v = part[mt][h2];
                v += __shfl_xor_sync(0xffffffffu, v, 1);
                v += __shfl_xor_sync(0xffffffffu, v, 2);
                if ((l & 3) == 0)
                    RS[ni * 128 + mi * 32 + mt * 16 + h2 * 8 + (l >> 2)] = v;
            }
        // store P to smem (swizzled)
#pragma unroll
        for (int mt = 0; mt < 2; mt++) {
            int row = mi * 32 + mt * 16 + (l >> 2);
#pragma unroll
            for (int nt = 0; nt < 4; nt++) {
                int col = ni * 32 + nt * 8 + 2 * (l & 3);
                int chunk = col >> 3, slot = (col & 7) * 2;
                *reinterpret_cast<uint32_t*>(sm + SM_P + row * 256 +
                    (((chunk ^ (row & 7)) << 4)) + slot) = pk[mt][nt][0];
                int row2 = row + 8;
                *reinterpret_cast<uint32_t*>(sm + SM_P + row2 * 256 +
                    (((chunk ^ (row2 & 7)) << 4)) + slot) = pk[mt][nt][1];
            }
        }
        __syncthreads();
        if (tid < 128)
            RT[tid] += RS[tid] + RS[128 + tid] + RS[256 + tid] + RS[384 + tid];

        // ---- PV : O[32m x 32c] += P[32m x 128n] * V[n][c]  (V tile == K tile) ----
#pragma unroll
        for (int ks = 0; ks < 8; ks++) {
            uint32_t af[2][4], bv[2][4];
            int chA = 2 * ks + hA;
#pragma unroll
            for (int mt = 0; mt < 2; mt++) LDSM_X4(af[mt], pbase[mt] + ((chA ^ swzA) << 4));
            uint32_t vb = vrowbase + ks * 4096;
#pragma unroll
            for (int ctp = 0; ctp < 2; ctp++) LDSM_X4_T(bv[ctp], vb + (((vchunk[ctp]) ^ swzA) << 4));
#pragma unroll
            for (int mt = 0; mt < 2; mt++)
#pragma unroll
                for (int ct = 0; ct < 4; ct++)
                    MMA_16816(oacc[mt][ct], af[mt], bv[ct >> 1][(ct & 1) * 2], bv[ct >> 1][(ct & 1) * 2 + 1]);
        }
        __syncthreads();  // protect K/P tiles before next iteration
    }

    // ---- epilogue: scale by gamma/rowsum, transpose via smem, add residual ----
    float* scratch = reinterpret_cast<float*>(sm + SM_K);   // 64KB: [c][m]
#pragma unroll
    for (int mt = 0; mt < 2; mt++) {
        int row  = mi * 32 + mt * 16 + (l >> 2);
        int row2 = row + 8;
        float s0 = gammav / RT[row];
        float s1 = gammav / RT[row2];
#pragma unroll
        for (int ct = 0; ct < 4; ct++) {
            int col = ni * 32 + ct * 8 + 2 * (l & 3);
            scratch[col * 128 + row]        = oacc[mt][ct][0] * s0;
            scratch[(col + 1) * 128 + row]  = oacc[mt][ct][1] * s0;
            scratch[col * 128 + row2]       = oacc[mt][ct][2] * s1;
            scratch[(col + 1) * 128 + row2] = oacc[mt][ct][3] * s1;
        }
    }
    __syncthreads();
    for (int i = tid; i < C_IN * 128; i += 512) {
        int c = i >> 7, m = i & 127;
        size_t gi = ((size_t)b * C_IN + c) * NPIX + m0 + m;
        out[gi] = scratch[c * 128 + m] + x[gi];
    }
}

// ================= launch =================
extern "C" void kernel_launch(void* const* d_in, const int* in_sizes, int n_in,
                              void* d_out, int out_size) {
    (void)in_sizes; (void)n_in; (void)out_size;
    const float* x     = (const float*)d_in[0];
    const float* Wb    = (const float*)d_in[1];
    const float* gamma = (const float*)d_in[2];
    float* out = (float*)d_out;

    cudaFuncSetAttribute(k1_project, cudaFuncAttributeMaxDynamicSharedMemorySize, 157728);
    cudaFuncSetAttribute(k2_attn,    cudaFuncAttributeMaxDynamicSharedMemorySize, SM2_TOTAL);

    k1_project<<<128, 256, 157728>>>(x, Wb);
    k2_attn<<<128, 512, SM2_TOTAL>>>(x, gamma, out);
}

// round 5
// speedup vs baseline: 1.4218x; 1.4218x over previous
#include <cuda_runtime.h>
#include <cuda_bf16.h>
#include <cstdint>
#include <cstddef>

#define BATCH 4
#define C_IN  124
#define CP    128
#define NPIX  4096
#define NIT   32

// ---------------- device scratch (zero-init) ----
__device__ __align__(128) __nv_bfloat16 g_hiT[BATCH * NPIX * CP];   // BfT [b][n][c] bf16
__device__ __align__(128) float         g_r2 [2][BATCH * NPIX];     // partial row norms

// ---------------- helpers ----------------
__device__ __forceinline__ uint32_t smem_u32(const void* p) {
    uint32_t a;
    asm("{ .reg .u64 t; cvta.to.shared.u64 t, %1; cvt.u32.u64 %0, t; }" : "=r"(a) : "l"(p));
    return a;
}
#define LDSM_X4(r, addr) \
    asm volatile("ldmatrix.sync.aligned.m8n8.x4.shared.b16 {%0,%1,%2,%3}, [%4];" \
        : "=r"((r)[0]), "=r"((r)[1]), "=r"((r)[2]), "=r"((r)[3]) : "r"(addr))
#define LDSM_X4_T(r, addr) \
    asm volatile("ldmatrix.sync.aligned.m8n8.x4.trans.shared.b16 {%0,%1,%2,%3}, [%4];" \
        : "=r"((r)[0]), "=r"((r)[1]), "=r"((r)[2]), "=r"((r)[3]) : "r"(addr))
#define MMA_16816(c, a, b0, b1) \
    asm volatile("mma.sync.aligned.m16n8k16.row.col.f32.bf16.bf16.f32 " \
        "{%0,%1,%2,%3}, {%4,%5,%6,%7}, {%8,%9}, {%0,%1,%2,%3};" \
        : "+f"((c)[0]), "+f"((c)[1]), "+f"((c)[2]), "+f"((c)[3]) \
        : "r"((a)[0]), "r"((a)[1]), "r"((a)[2]), "r"((a)[3]), "r"(b0), "r"(b1))

#define CP_ASYNC16(dst, src) \
    asm volatile("cp.async.cg.shared.global [%0], [%1], 16;" :: "r"(dst), "l"(src) : "memory")
#define CP_COMMIT() asm volatile("cp.async.commit_group;" ::: "memory")
#define CP_WAIT(n)  asm volatile("cp.async.wait_group %0;" :: "n"(n) : "memory")

__device__ __forceinline__ uint32_t pack_bf16x2(float even, float odd) {
    uint32_t r;
    asm("cvt.rn.satfinite.bf16x2.f32 %0, %1, %2;" : "=r"(r) : "f"(odd), "f"(even));
    return r;  // low half = even
}
__device__ __forceinline__ float bf_lo(uint32_t u) { return __uint_as_float(u << 16); }
__device__ __forceinline__ float bf_hi(uint32_t u) { return __uint_as_float(u & 0xffff0000u); }

// async-copy a [128 rows][128 bf16] row-major tile into swizzled smem
__device__ __forceinline__ void copy_tile_async(uint32_t dst, const __nv_bfloat16* src,
                                                int tid) {
    for (int idx = tid; idx < 2048; idx += 256) {
        int row = idx >> 4;
        int ch  = idx & 15;
        uint32_t d = dst + row * 256 + (((ch ^ (row & 7)) << 4));
        CP_ASYNC16(d, src + (size_t)row * CP + (ch << 3));
    }
}

// ================= kernel 1: BfT = (Wb @ x)^T bf16, + row norms =================
// grid 128 = b(4) x ntile(16) x co-half(2); block 128; each thread 2 pixels, 62 c-outs.
__global__ void __launch_bounds__(128, 1)
k1_project(const float* __restrict__ x, const float* __restrict__ Wb) {
    extern __shared__ float sm1[];
    float* xs = sm1;                  // [124][256]
    float* ws = sm1 + 124 * 256;      // [62][124]

    int blk  = blockIdx.x;
    int half = blk & 1;
    int nt   = (blk >> 1) & 15;
    int b    = blk >> 5;
    int n0   = nt * 256;
    int co0  = half * 62;
    int tid  = threadIdx.x;

    // x tile: 124 rows x 64 float4
    for (int idx = tid; idx < 124 * 64; idx += 128) {
        int ci = idx >> 6, j4 = idx & 63;
        reinterpret_cast<float4*>(xs)[idx] =
            *reinterpret_cast<const float4*>(x + ((size_t)b * C_IN + ci) * NPIX + n0 + (j4 << 2));
    }
    for (int idx = tid; idx < 62 * 124; idx += 128)
        ws[idx] = Wb[(size_t)(co0 + idx / 124) * C_IN + (idx % 124)];
    __syncthreads();

    float acc0[62], acc1[62];
#pragma unroll
    for (int j = 0; j < 62; j++) { acc0[j] = 0.f; acc1[j] = 0.f; }
    int p0 = 2 * tid, p1 = 2 * tid + 1;
    for (int ci = 0; ci < 124; ci++) {
        float2 xv = *reinterpret_cast<const float2*>(&xs[ci * 256 + p0]);
#pragma unroll
        for (int j = 0; j < 62; j++) {
            float w = ws[j * 124 + ci];
            acc0[j] += w * xv.x;
            acc1[j] += w * xv.y;
        }
    }
    __syncthreads();  // xs region reusable

    __nv_bfloat16* shh = reinterpret_cast<__nv_bfloat16*>(sm1);  // [256][62]
    float r0 = 0.f, r1 = 0.f;
#pragma unroll
    for (int j = 0; j < 62; j++) {
        __nv_bfloat16 h0 = __float2bfloat16(acc0[j]);
        __nv_bfloat16 h1 = __float2bfloat16(acc1[j]);
        float f0 = __bfloat162float(h0), f1 = __bfloat162float(h1);
        r0 += f0 * f0;
        r1 += f1 * f1;
        shh[p0 * 62 + j] = h0;
        shh[p1 * 62 + j] = h1;
    }
    g_r2[half][b * NPIX + n0 + p0] = r0;
    g_r2[half][b * NPIX + n0 + p1] = r1;
    __syncthreads();

    for (int idx = tid; idx < 256 * 62; idx += 128) {
        int p = idx / 62, jj = idx - p * 62;
        g_hiT[((size_t)b * NPIX + n0 + p) * CP + co0 + jj] = shh[idx];
    }
}

// ================= kernel 2: fused flash attention, register-P =================
// grid 128 = b(4) x m-tile(32); block 256 = 8 warps, each warp = m16 x n128.
#define SMK0 0
#define SMK1 32768
#define SMQ  65536
#define SM2_TOTAL 98304

__global__ void __launch_bounds__(256, 1)
k2_attn(const float* __restrict__ x, const float* __restrict__ gamma,
        float* __restrict__ out) {
    extern __shared__ char sm[];
    uint32_t sb = smem_u32(sm);

    int tid = threadIdx.x;
    int l   = tid & 31, wid = tid >> 5;
    int b   = blockIdx.x >> 5;
    int m0  = (blockIdx.x & 31) * 128;

    const __nv_bfloat16* hiT = g_hiT + (size_t)b * NPIX * CP;

    // ldmatrix lane address components
    int rowA = l & 15, hA = l >> 4, swzA = rowA & 7;      // A / trans-B pattern
    int rowB = (l & 7) + ((l >> 4) << 3);                 // B (K) pattern
    int pB   = (l >> 3) & 1, swzB = rowB & 7;
    int g    = l >> 2;                                     // quad group (row in m8)

    // prologue: async-load Q, tile0, tile1
    copy_tile_async(sb + SMQ,  hiT + (size_t)m0 * CP, tid); CP_COMMIT();
    copy_tile_async(sb + SMK0, hiT,                  tid); CP_COMMIT();
    copy_tile_async(sb + SMK1, hiT + (size_t)128 * CP, tid); CP_COMMIT();

    float gammav = gamma[0];
    int r_g  = m0 + wid * 16 + g;
    float rr0 = g_r2[0][b * NPIX + r_g]     + g_r2[1][b * NPIX + r_g];
    float rr1 = g_r2[0][b * NPIX + r_g + 8] + g_r2[1][b * NPIX + r_g + 8];

    CP_WAIT(2);
    __syncthreads();

    // hoist Q fragments: m16 x k128 = 8 k-steps x 4 regs
    uint32_t qf[8][4];
    uint32_t qrow = sb + SMQ + (wid * 16 + rowA) * 256;
#pragma unroll
    for (int ks = 0; ks < 8; ks++)
        LDSM_X4(qf[ks], qrow + (((2 * ks + hA) ^ swzA) << 4));

    float oacc[16][4];
#pragma unroll
    for (int cc = 0; cc < 16; cc++)
#pragma unroll
        for (int d = 0; d < 4; d++) oacc[cc][d] = 0.f;
    float rsum0 = 0.f, rsum1 = 0.f;

    uint32_t browB = rowB * 256, browA = rowA * 256;

    for (int it = 0; it < NIT; it++) {
        CP_WAIT(1);
        __syncthreads();
        uint32_t kb = sb + ((it & 1) ? SMK1 : SMK0);

        // ---- QK^T + softmax, per n16 group; P packed straight into A-fragments ----
        uint32_t pA[8][4];
#pragma unroll
        for (int nn = 0; nn < 8; nn++) {
            float s0[4] = {0.f, 0.f, 0.f, 0.f};
            float s1[4] = {0.f, 0.f, 0.f, 0.f};
            uint32_t kbn = kb + (uint32_t)(nn * 16) * 256 + browB;
#pragma unroll
            for (int ks = 0; ks < 8; ks++) {
                uint32_t bf[4];
                LDSM_X4(bf, kbn + (((2 * ks + pB) ^ swzB) << 4));
                MMA_16816(s0, qf[ks], bf[0], bf[1]);
                MMA_16816(s1, qf[ks], bf[2], bf[3]);
            }
            float e0 = __expf(s0[0] - rr0), e1 = __expf(s0[1] - rr0);
            float e2 = __expf(s0[2] - rr1), e3 = __expf(s0[3] - rr1);
            float f0 = __expf(s1[0] - rr0), f1 = __expf(s1[1] - rr0);
            float f2 = __expf(s1[2] - rr1), f3 = __expf(s1[3] - rr1);
            pA[nn][0] = pack_bf16x2(e0, e1);
            pA[nn][1] = pack_bf16x2(e2, e3);
            pA[nn][2] = pack_bf16x2(f0, f1);
            pA[nn][3] = pack_bf16x2(f2, f3);
            rsum0 += bf_lo(pA[nn][0]) + bf_hi(pA[nn][0]) + bf_lo(pA[nn][2]) + bf_hi(pA[nn][2]);
            rsum1 += bf_lo(pA[nn][1]) + bf_hi(pA[nn][1]) + bf_lo(pA[nn][3]) + bf_hi(pA[nn][3]);
        }

        // ---- PV: O += P[m16 x n128] * V[n128 x c128]  (V tile == K tile, trans) ----
#pragma unroll
        for (int nn = 0; nn < 8; nn++) {
            uint32_t vbn = kb + (uint32_t)(nn * 16) * 256 + browA;
#pragma unroll
            for (int cc = 0; cc < 8; cc++) {
                uint32_t bv[4];
                LDSM_X4_T(bv, vbn + (((2 * cc + hA) ^ swzA) << 4));
                MMA_16816(oacc[2 * cc],     pA[nn], bv[0], bv[1]);
                MMA_16816(oacc[2 * cc + 1], pA[nn], bv[2], bv[3]);
            }
        }
        __syncthreads();
        if (it + 2 < NIT)
            copy_tile_async(sb + ((it & 1) ? SMK1 : SMK0), hiT + (size_t)(it + 2) * 128 * CP, tid);
        CP_COMMIT();
    }

    // ---- epilogue ----
    rsum0 += __shfl_xor_sync(0xffffffffu, rsum0, 1);
    rsum0 += __shfl_xor_sync(0xffffffffu, rsum0, 2);
    rsum1 += __shfl_xor_sync(0xffffffffu, rsum1, 1);
    rsum1 += __shfl_xor_sync(0xffffffffu, rsum1, 2);
    float s0 = gammav / rsum0, s1 = gammav / rsum1;

    float* sc = reinterpret_cast<float*>(sm);   // [128 c][132 m] padded stride
    int row = wid * 16 + g;
#pragma unroll
    for (int cc = 0; cc < 16; cc++) {
        int c = cc * 8 + 2 * (l & 3);
        sc[c * 132 + row]           = oacc[cc][0] * s0;
        sc[(c + 1) * 132 + row]     = oacc[cc][1] * s0;
        sc[c * 132 + row + 8]       = oacc[cc][2] * s1;
        sc[(c + 1) * 132 + row + 8] = oacc[cc][3] * s1;
    }
    __syncthreads();
    for (int i = tid; i < C_IN * 128; i += 256) {
        int c = i >> 7, m = i & 127;
        size_t gi = ((size_t)b * C_IN + c) * NPIX + m0 + m;
        out[gi] = sc[c * 132 + m] + x[gi];
    }
}

// ================= launch =================
extern "C" void kernel_launch(void* const* d_in, const int* in_sizes, int n_in,
                              void* d_out, int out_size) {
    (void)in_sizes; (void)n_in; (void)out_size;
    const float* x     = (const float*)d_in[0];
    const float* Wb    = (const float*)d_in[1];
    const float* gamma = (const float*)d_in[2];
    float* out = (float*)d_out;

    cudaFuncSetAttribute(k1_project, cudaFuncAttributeMaxDynamicSharedMemorySize, 157728);
    cudaFuncSetAttribute(k2_attn,    cudaFuncAttributeMaxDynamicSharedMemorySize, SM2_TOTAL);

    k1_project<<<128, 128, 157728>>>(x, Wb);
    k2_attn<<<128, 256, SM2_TOTAL>>>(x, gamma, out);
}